// round 1
// baseline (speedup 1.0000x reference)
#include <cuda_runtime.h>
#include <cstdint>

#define BB 256
#define SS 2048
#define FF 64
#define ORD 5
#define KD  (ORD*FF)   // 320

// per-(b,f) mean of observed entries — scratch (no allocation allowed)
__device__ float g_mean[BB * FF];

// ---------------------------------------------------------------------------
// Pre-pass: mean[b,f] = sum_s x*mask / (sum_s mask + 1e-8)
// ---------------------------------------------------------------------------
__global__ __launch_bounds__(256) void mean_kernel(const float* __restrict__ x,
                                                   const int* __restrict__ mask) {
    int b = blockIdx.x;
    int f = threadIdx.x & 63;
    int c = threadIdx.x >> 6;          // 4 chunks of 512 steps
    const float* xb = x    + (size_t)b * SS * FF;
    const int*   mb = mask + (size_t)b * SS * FF;

    float sum = 0.f;
    int   cnt = 0;
    int s0 = c * (SS / 4), s1 = s0 + (SS / 4);
    for (int s = s0; s < s1; s++) {
        int idx = s * FF + f;
        int m = mb[idx];
        float xv = xb[idx];
        if (m) { sum += xv; cnt++; }
    }

    __shared__ float ssum[4][64];
    __shared__ int   scnt[4][64];
    ssum[c][f] = sum;
    scnt[c][f] = cnt;
    __syncthreads();
    if (threadIdx.x < 64) {
        float s4 = ssum[0][f] + ssum[1][f] + ssum[2][f] + ssum[3][f];
        int   c4 = scnt[0][f] + scnt[1][f] + scnt[2][f] + scnt[3][f];
        g_mean[b * FF + f] = s4 / ((float)c4 + 1e-8f);
    }
}

// ---------------------------------------------------------------------------
// Main recurrence: one CTA per batch, 64 features x 4 lanes.
// W register-resident as f32x2 pairs; window double-buffered in SMEM.
// ---------------------------------------------------------------------------
__global__ __launch_bounds__(256, 2) void var_kernel(
    const float* __restrict__ x, const int* __restrict__ mask,
    const float* __restrict__ W, const float* __restrict__ bias,
    float* __restrict__ out)
{
    int b   = blockIdx.x;
    int tid = threadIdx.x;
    int f   = tid >> 2;     // 0..63  output feature
    int q   = tid & 3;      // 0..3   K-split lane

    __shared__ __align__(16) float win[2][KD];

    // Load this thread's 80 W coefficients (chunks c = q + 4r, 4 floats each)
    // packed into 40 f32x2 register pairs.
    uint64_t w2[40];
    {
        const float4* Wf = (const float4*)(W + (size_t)f * KD);
        #pragma unroll
        for (int r = 0; r < 20; r++) {
            float4 wv = Wf[q + 4 * r];
            asm("mov.b64 %0, {%1,%2};" : "=l"(w2[2*r])   : "f"(wv.x), "f"(wv.y));
            asm("mov.b64 %0, {%1,%2};" : "=l"(w2[2*r+1]) : "f"(wv.z), "f"(wv.w));
        }
    }
    float bv = bias[f];

    // Initial window: every slot = per-feature mean
    for (int i = tid; i < KD; i += 256)
        win[0][i] = g_mean[b * FF + (i & 63)];

    const float* xb = x    + (size_t)b * SS * FF;
    const int*   mb = mask + (size_t)b * SS * FF;
    float*       ob = out  + (size_t)b * SS * FF;

    // Prefetch step 0
    float xv = 0.f; int mv = 0;
    if (q == 0) { xv = xb[f]; mv = mb[f]; }
    __syncthreads();

    int p = 0;
    for (int t = 0; t < SS; t++) {
        const float4* wp = (const float4*)(win[p]) + q;
        uint64_t acc0 = 0ull, acc1 = 0ull;   // f32x2 {0,0}
        #pragma unroll
        for (int r = 0; r < 20; r++) {
            float4 v = wp[4 * r];            // LDS.128, broadcast conflict-free
            uint64_t v01, v23;
            asm("mov.b64 %0, {%1,%2};" : "=l"(v01) : "f"(v.x), "f"(v.y));
            asm("mov.b64 %0, {%1,%2};" : "=l"(v23) : "f"(v.z), "f"(v.w));
            asm("fma.rn.f32x2 %0, %1, %2, %0;" : "+l"(acc0) : "l"(w2[2*r]),   "l"(v01));
            asm("fma.rn.f32x2 %0, %1, %2, %0;" : "+l"(acc1) : "l"(w2[2*r+1]), "l"(v23));
        }
        uint64_t acc;
        asm("add.rn.f32x2 %0, %1, %2;" : "=l"(acc) : "l"(acc0), "l"(acc1));
        float lo, hi;
        asm("mov.b64 {%0,%1}, %2;" : "=f"(lo), "=f"(hi) : "l"(acc));
        float s = lo + hi;
        // reduce over the 4 K-split lanes (quad lives inside one warp)
        s += __shfl_xor_sync(0xffffffffu, s, 1);
        s += __shfl_xor_sync(0xffffffffu, s, 2);
        float xhat = s + bv;

        float nv = 0.f;
        if (q == 0) {
            nv = mv ? xv : xhat;             // keep observed, impute missing
            ob[t * FF + f] = nv;
            if (t + 1 < SS) {                // prefetch next step
                xv = xb[(t + 1) * FF + f];
                mv = mb[(t + 1) * FF + f];
            }
        }

        // Build next window in the other buffer: shift left one slot, append nv
        int pn = p ^ 1;
        float shifted = win[p][tid + 64];
        win[pn][tid] = shifted;
        if (q == 0) win[pn][4 * FF + f] = nv;
        __syncthreads();
        p = pn;
    }
}

// ---------------------------------------------------------------------------
extern "C" void kernel_launch(void* const* d_in, const int* in_sizes, int n_in,
                              void* d_out, int out_size) {
    const float* x    = (const float*)d_in[0];
    const int*   mask = (const int*)  d_in[1];
    const float* W    = (const float*)d_in[2];
    const float* bias = (const float*)d_in[3];
    float*       out  = (float*)d_out;

    mean_kernel<<<BB, 256>>>(x, mask);
    var_kernel<<<BB, 256>>>(x, mask, W, bias, out);
}

// round 4
// speedup vs baseline: 2.7823x; 2.7823x over previous
#include <cuda_runtime.h>
#include <cstdint>

#define BB 256
#define SS 2048
#define FF 64
#define KD 320   // ORDER * FF

// per-(b,f) mean of observed entries — scratch (no allocation allowed)
__device__ __align__(256) float g_mean[BB * FF];

// ---------------------------------------------------------------------------
// Pre-pass: mean[b,f] = sum_s x*mask / (sum_s mask + 1e-8)
// ---------------------------------------------------------------------------
__global__ __launch_bounds__(256) void mean_kernel(const float* __restrict__ x,
                                                   const int* __restrict__ mask) {
    int b = blockIdx.x;
    int f = threadIdx.x & 63;
    int c = threadIdx.x >> 6;          // 4 chunks of 512 steps
    const float* xb = x    + (size_t)b * SS * FF;
    const int*   mb = mask + (size_t)b * SS * FF;

    float sum = 0.f;
    int   cnt = 0;
    int s0 = c * (SS / 4), s1 = s0 + (SS / 4);
    for (int s = s0; s < s1; s++) {
        int idx = s * FF + f;
        int m = mb[idx];
        float xv = xb[idx];
        if (m) { sum += xv; cnt++; }
    }

    __shared__ float ssum[4][64];
    __shared__ int   scnt[4][64];
    ssum[c][f] = sum;
    scnt[c][f] = cnt;
    __syncthreads();
    if (threadIdx.x < 64) {
        float s4 = ssum[0][f] + ssum[1][f] + ssum[2][f] + ssum[3][f];
        int   c4 = scnt[0][f] + scnt[1][f] + scnt[2][f] + scnt[3][f];
        g_mean[b * FF + f] = s4 / ((float)c4 + 1e-8f);
    }
}

// ---------------------------------------------------------------------------
// f32x2 helpers
// ---------------------------------------------------------------------------
__device__ __forceinline__ uint64_t pack2(float a, float b) {
    uint64_t r; asm("mov.b64 %0,{%1,%2};" : "=l"(r) : "f"(a), "f"(b)); return r;
}
__device__ __forceinline__ void fma2(uint64_t& acc, uint64_t a, uint64_t b) {
    asm("fma.rn.f32x2 %0, %1, %2, %0;" : "+l"(acc) : "l"(a), "l"(b));
}
__device__ __forceinline__ float hadd2(uint64_t v) {
    float lo, hi; asm("mov.b64 {%0,%1}, %2;" : "=f"(lo), "=f"(hi) : "l"(v));
    return lo + hi;
}

// ---------------------------------------------------------------------------
// Main recurrence. One CTA (128 threads) per batch, 256 CTAs, 2 CTAs/SM,
// single wave. Thread = (fg, q): fg = group of 4 contiguous output features,
// q = K-octant (8 floats/frame). W register-resident (80 f32x2/thread);
// window register-cached as 5 circular 8-float frame slices; only the newest
// frame is re-read from smem each step (2 LDS.128). One barrier per step.
// Tail: 2045 = 5*409 main iterations + 3-phase peeled epilogue (no mid-loop
// return).
// ---------------------------------------------------------------------------
__global__ __launch_bounds__(128, 2) void var_kernel(
    const float* __restrict__ x, const int* __restrict__ mask,
    const float* __restrict__ W, const float* __restrict__ bias,
    float* __restrict__ out)
{
    int tid = threadIdx.x;
    int b   = blockIdx.x;
    int fg  = tid >> 3;     // 0..15 feature group
    int q   = tid & 7;      // 0..7  K-octant
    int f0  = fg << 2;
    int ko  = q << 3;

    __shared__ __align__(16) float win[5][FF];   // circular frame buffer

    // W registers: w[g][frame-row j][pair]
    uint64_t w[4][5][4];
    #pragma unroll
    for (int g = 0; g < 4; g++) {
        #pragma unroll
        for (int j = 0; j < 5; j++) {
            const float4* p4 = (const float4*)(W + (size_t)(f0 + g) * KD + j * FF + ko);
            float4 a = p4[0], c = p4[1];
            w[g][j][0] = pack2(a.x, a.y); w[g][j][1] = pack2(a.z, a.w);
            w[g][j][2] = pack2(c.x, c.y); w[g][j][3] = pack2(c.z, c.w);
        }
    }
    float4 bias4 = *(const float4*)(bias + f0);

    // smem window init: per-feature means
    for (int i = tid; i < 5 * FF; i += 128)
        (&win[0][0])[i] = g_mean[b * FF + (i & 63)];

    // register window cache: all 5 slots = mean slice
    uint64_t wr[5][4];
    {
        const float4* mp = (const float4*)(g_mean + b * FF + ko);
        float4 a = mp[0], c = mp[1];
        #pragma unroll
        for (int j = 0; j < 5; j++) {
            wr[j][0] = pack2(a.x, a.y); wr[j][1] = pack2(a.z, a.w);
            wr[j][2] = pack2(c.x, c.y); wr[j][3] = pack2(c.z, c.w);
        }
    }

    const float4* xb = (const float4*)(x    + (size_t)b * SS * FF);
    const int4*   mb = (const int4*)  (mask + (size_t)b * SS * FF);
    float4*       ob = (float4*)      (out  + (size_t)b * SS * FF);

    // Prefetch step 0 (8 q-lanes load the same float4 — broadcast)
    float4 xv = xb[fg];
    int4   mv = mb[fg];

    __syncthreads();

    int t = 0;

    // One recurrence step at static phase P. Advances t by 1.
    #define STEP(P)                                                            \
    do {                                                                       \
        /* refresh: slot (P+4)%5 holds the newest frame */                     \
        {                                                                      \
            const float4* nf = (const float4*)(&win[(P + 4) % 5][ko]);         \
            float4 a = nf[0], c = nf[1];                                       \
            wr[(P + 4) % 5][0] = pack2(a.x, a.y);                              \
            wr[(P + 4) % 5][1] = pack2(a.z, a.w);                              \
            wr[(P + 4) % 5][2] = pack2(c.x, c.y);                              \
            wr[(P + 4) % 5][3] = pack2(c.z, c.w);                              \
        }                                                                      \
        uint64_t acc0 = 0, acc1 = 0, acc2 = 0, acc3 = 0;                       \
        _Pragma("unroll")                                                      \
        for (int s = 0; s < 5; s++) {                                          \
            const int jp = (s - (P) + 5) % 5;                                  \
            _Pragma("unroll")                                                  \
            for (int o = 0; o < 4; o++) {                                      \
                fma2(acc0, w[0][jp][o], wr[s][o]);                             \
                fma2(acc1, w[1][jp][o], wr[s][o]);                             \
                fma2(acc2, w[2][jp][o], wr[s][o]);                             \
                fma2(acc3, w[3][jp][o], wr[s][o]);                             \
            }                                                                  \
        }                                                                      \
        float r0 = hadd2(acc0), r1 = hadd2(acc1);                              \
        float r2 = hadd2(acc2), r3 = hadd2(acc3);                              \
        _Pragma("unroll")                                                      \
        for (int d = 1; d < 8; d <<= 1) {                                      \
            r0 += __shfl_xor_sync(0xffffffffu, r0, d);                         \
            r1 += __shfl_xor_sync(0xffffffffu, r1, d);                         \
            r2 += __shfl_xor_sync(0xffffffffu, r2, d);                         \
            r3 += __shfl_xor_sync(0xffffffffu, r3, d);                         \
        }                                                                      \
        float4 nv;                                                             \
        nv.x = mv.x ? xv.x : (r0 + bias4.x);                                   \
        nv.y = mv.y ? xv.y : (r1 + bias4.y);                                   \
        nv.z = mv.z ? xv.z : (r2 + bias4.z);                                   \
        nv.w = mv.w ? xv.w : (r3 + bias4.w);                                   \
        if (q == 0) {                                                          \
            *(float4*)(&win[(P)][f0]) = nv;   /* oldest slot <- newest */      \
            ob[(size_t)t * 16 + fg] = nv;                                      \
        }                                                                      \
        if (t + 1 < SS) {                                                      \
            xv = xb[(size_t)(t + 1) * 16 + fg];                                \
            mv = mb[(size_t)(t + 1) * 16 + fg];                                \
        }                                                                      \
        __syncthreads();                                                       \
        t++;                                                                   \
    } while (0)

    // 409 * 5 = 2045 steps
    for (int it = 0; it < 409; it++) {
        STEP(0); STEP(1); STEP(2); STEP(3); STEP(4);
    }
    // epilogue: t = 2045, 2046, 2047 (phases 0,1,2 since 2045 % 5 == 0)
    STEP(0); STEP(1); STEP(2);

    #undef STEP
}

// ---------------------------------------------------------------------------
extern "C" void kernel_launch(void* const* d_in, const int* in_sizes, int n_in,
                              void* d_out, int out_size) {
    const float* x    = (const float*)d_in[0];
    const int*   mask = (const int*)  d_in[1];
    const float* W    = (const float*)d_in[2];
    const float* bias = (const float*)d_in[3];
    float*       out  = (float*)d_out;

    mean_kernel<<<BB, 256>>>(x, mask);
    var_kernel<<<BB, 128>>>(x, mask, W, bias, out);
}